// round 2
// baseline (speedup 1.0000x reference)
#include <cuda_runtime.h>
#include <math.h>
#include <stdint.h>

#define NN   2048
#define KK   16384      // NN * 8
#define TAU  10
#define NB   8

// dense trace for layer 0
__device__ __align__(16) float g_x0[KK];
// split-K partials for layer 0 (row, half)
__device__ float g_part[NN][2];
// compacted active-spike index lists for layers 1 and 2
__device__ int g_idx[2][NN];
__device__ int g_cnt[2];

// ---------------- Threefry-2x32 (JAX-compatible, 20 rounds) ----------------
__host__ __device__ inline uint32_t tf_rotl(uint32_t v, int r) {
    return (v << r) | (v >> (32 - r));
}

__host__ __device__ inline void tf_block(uint32_t k0, uint32_t k1,
                                         uint32_t c0, uint32_t c1,
                                         uint32_t& o0, uint32_t& o1) {
    uint32_t ks2 = k0 ^ k1 ^ 0x1BD11BDAu;
    uint32_t x0 = c0 + k0, x1 = c1 + k1;
#define TF_RND(r) { x0 += x1; x1 = tf_rotl(x1, (r)); x1 ^= x0; }
    TF_RND(13) TF_RND(15) TF_RND(26) TF_RND(6)
    x0 += k1;  x1 += ks2 + 1u;
    TF_RND(17) TF_RND(29) TF_RND(16) TF_RND(24)
    x0 += ks2; x1 += k0 + 2u;
    TF_RND(13) TF_RND(15) TF_RND(26) TF_RND(6)
    x0 += k0;  x1 += k1 + 3u;
    TF_RND(17) TF_RND(29) TF_RND(16) TF_RND(24)
    x0 += k1;  x1 += ks2 + 4u;
    TF_RND(13) TF_RND(15) TF_RND(26) TF_RND(6)
    x0 += ks2; x1 += k0 + 5u;
#undef TF_RND
    o0 = x0; o1 = x1;
}

__device__ inline float tf_uniform(uint32_t k0, uint32_t k1, uint32_t e) {
    uint32_t b1, b2;
    tf_block(k0, k1, 0u, e, b1, b2);
    uint32_t bits = b1 ^ b2;
    return __uint_as_float((bits >> 9) | 0x3f800000u) - 1.0f;
}

// ---------------- Kernel 1: layer-0 input trace ----------------
__global__ void trace_kernel(const float* __restrict__ inp) {
    __shared__ float filt[TAU * NB];
    int tid = threadIdx.x;
    if (tid < TAU * NB) {
        int t = tid / NB, b = tid % NB;
        const float mupi = 1.5707963267948966f;
        const float pif  = 3.14159265358979f;
        float arg = mupi * log1pf((float)t) - mupi * (float)b;
        arg = fminf(fmaxf(arg, -pif), pif);
        filt[tid] = 0.5f * (1.0f + cosf(arg));
    }
    __syncthreads();
    int i = blockIdx.x * blockDim.x + tid;
    if (i < NN) {
        float acc[NB];
#pragma unroll
        for (int b = 0; b < NB; b++) acc[b] = 0.0f;
#pragma unroll
        for (int t = 0; t < TAU; t++) {
            float v = inp[i * TAU + (TAU - 1 - t)];
#pragma unroll
            for (int b = 0; b < NB; b++) acc[b] += v * filt[t * NB + b];
        }
#pragma unroll
        for (int b = 0; b < NB; b++) g_x0[i * NB + b] = acc[b];
    }
}

// block-wide reduce of one float over 256 threads; result valid in thread 0
__device__ inline float block_reduce_256(float acc) {
    __shared__ float warpsum[8];
#pragma unroll
    for (int off = 16; off > 0; off >>= 1)
        acc += __shfl_down_sync(0xffffffffu, acc, off);
    int lane = threadIdx.x & 31, wid = threadIdx.x >> 5;
    if (lane == 0) warpsum[wid] = acc;
    __syncthreads();
    float tot = 0.0f;
    if (threadIdx.x == 0) {
#pragma unroll
        for (int w = 0; w < 8; w++) tot += warpsum[w];
    }
    return tot;
}

// ---------------- Kernel 2: layer-0 dense matvec, half-row per block -------
__global__ __launch_bounds__(256) void l0_part(const float* __restrict__ W) {
    const int row  = blockIdx.x >> 1;
    const int half = blockIdx.x & 1;
    const float4* w4 = reinterpret_cast<const float4*>(W + (size_t)row * KK) + half * 2048;
    const float4* x4 = reinterpret_cast<const float4*>(g_x0) + half * 2048;

    float acc = 0.0f;
#pragma unroll
    for (int it = 0; it < 8; it++) {
        int j = it * 256 + threadIdx.x;
        float4 w = w4[j];
        float4 xv = x4[j];
        acc += w.x * xv.x + w.y * xv.y + w.z * xv.z + w.w * xv.w;
    }
    float tot = block_reduce_256(acc);
    if (threadIdx.x == 0) g_part[row][half] = tot;
}

// scan helper: given per-thread count c (1024 threads), produce exclusive
// prefix; returns exclusive offset, and total in *total (valid everywhere).
__device__ inline int block_scan_1024(int c, int* sh, int* total) {
    int t = threadIdx.x;
    sh[t] = c;
    __syncthreads();
#pragma unroll
    for (int off = 1; off < 1024; off <<= 1) {
        int v = (t >= off) ? sh[t - off] : 0;
        __syncthreads();
        sh[t] += v;
        __syncthreads();
    }
    int incl = sh[t];
    *total = sh[1023];
    return incl - c;
}

// ---------------- Kernel 3: layer-0 finish + build active list ------------
// 1 block, 1024 threads, 2 neurons each.
__global__ __launch_bounds__(1024) void finish0(
    const float* __restrict__ bias,
    float* __restrict__ p_out, float* __restrict__ s_out,
    uint32_t key0, uint32_t key1)
{
    __shared__ int sh[1024];
    int t = threadIdx.x;
    float sv[2];
    int c = 0;
#pragma unroll
    for (int q = 0; q < 2; q++) {
        int e = 2 * t + q;
        float pot = g_part[e][0] + g_part[e][1] + bias[e];
        float p = 1.0f / (1.0f + expf(-pot));
        float u = tf_uniform(key0, key1, (uint32_t)e);
        float s = (u < p) ? 1.0f : 0.0f;
        p_out[e] = p;
        s_out[e] = s;
        sv[q] = s;
        c += (s > 0.0f);
    }
    int total;
    int o = block_scan_1024(c, sh, &total);
#pragma unroll
    for (int q = 0; q < 2; q++) {
        if (sv[q] > 0.0f) g_idx[0][o++] = 2 * t + q;
    }
    if (t == 0) g_cnt[0] = total;
}

// ---------------- Kernel 4: sparse-gather layer (layers 1 and 2) ----------
// pot[row] = sum over active i of (W[row,i,0] + f1 * W[row,i,1])
__global__ __launch_bounds__(256) void layer_gather(
    const float* __restrict__ W, const float* __restrict__ bias,
    int list, float* __restrict__ p_out, float* __restrict__ s_out,
    uint32_t key0, uint32_t key1, float f1)
{
    const int row = blockIdx.x;
    const int cnt = g_cnt[list];
    const int* __restrict__ idx = g_idx[list];
    const float2* __restrict__ w2 =
        reinterpret_cast<const float2*>(W + (size_t)row * KK);

    float acc = 0.0f;
    for (int i = threadIdx.x; i < cnt; i += 256) {
        int ii = idx[i];
        float2 v = w2[(size_t)ii * 4];   // W[row, ii, 0..1]
        acc += v.x + f1 * v.y;
    }
    float tot = block_reduce_256(acc);
    if (threadIdx.x == 0) {
        float z = tot + bias[row];
        float p = 1.0f / (1.0f + expf(-z));
        float u = tf_uniform(key0, key1, (uint32_t)row);
        float s = (u < p) ? 1.0f : 0.0f;
        p_out[row] = p;
        s_out[row] = s;
    }
}

// ---------------- Kernel 5: compaction of spike vector into index list ----
__global__ __launch_bounds__(1024) void compact(const float* __restrict__ s_in,
                                                int list)
{
    __shared__ int sh[1024];
    int t = threadIdx.x;
    float sv[2];
    int c = 0;
#pragma unroll
    for (int q = 0; q < 2; q++) {
        sv[q] = s_in[2 * t + q];
        c += (sv[q] > 0.0f);
    }
    int total;
    int o = block_scan_1024(c, sh, &total);
#pragma unroll
    for (int q = 0; q < 2; q++) {
        if (sv[q] > 0.0f) g_idx[list][o++] = 2 * t + q;
    }
    if (t == 0) g_cnt[list] = total;
}

extern "C" void kernel_launch(void* const* d_in, const int* in_sizes, int n_in,
                              void* d_out, int out_size) {
    const float* inp  = (const float*)d_in[0];
    const float* ffw0 = (const float*)d_in[1];
    const float* b0   = (const float*)d_in[3];
    const float* ffw1 = (const float*)d_in[4];
    const float* b1   = (const float*)d_in[6];
    const float* ffw2 = (const float*)d_in[7];
    const float* b2   = (const float*)d_in[9];
    float* out = (float*)d_out;

    // root key = (0, 42); partitionable split: key_i = block(root, (0, i))
    uint32_t k0a, k0b, k1a, k1b, k2a, k2b;
    tf_block(0u, 42u, 0u, 0u, k0a, k0b);
    tf_block(0u, 42u, 0u, 1u, k1a, k1b);
    tf_block(0u, 42u, 0u, 2u, k2a, k2b);

    // FF_FILT[0, 1]; b>=2 entries are exactly 0 (clip to -pi), b=0 is 1.0
    const float mupi = 1.5707963267948966f;
    const float pif  = 3.14159265358979f;
    float f1 = 0.5f * (1.0f + cosf(fminf(fmaxf(-mupi, -pif), pif)));  // 0.5

    // output layout: [p2 | s2 | p0 | p1 | s0 | s1], 6 * 2048 floats
    float* p2 = out;
    float* s2 = out + 2048;
    float* p0 = out + 4096;
    float* p1 = out + 6144;
    float* s0 = out + 8192;
    float* s1 = out + 10240;

    trace_kernel<<<16, 128>>>(inp);
    l0_part<<<2 * NN, 256>>>(ffw0);
    finish0<<<1, 1024>>>(b0, p0, s0, k0a, k0b);
    layer_gather<<<NN, 256>>>(ffw1, b1, 0, p1, s1, k1a, k1b, f1);
    compact<<<1, 1024>>>(s1, 1);
    layer_gather<<<NN, 256>>>(ffw2, b2, 1, p2, s2, k2a, k2b, f1);
}

// round 3
// speedup vs baseline: 1.1609x; 1.1609x over previous
#include <cuda_runtime.h>
#include <math.h>
#include <stdint.h>

#define NN   2048
#define KK   16384      // NN * 8
#define TAU  10
#define NB   8

// x-vectors for the three matvecs (trace0, spikes0-expanded, spikes1-expanded)
__device__ __align__(16) float g_x[3][KK];

// ---------------- Threefry-2x32 (JAX-compatible, 20 rounds) ----------------
__host__ __device__ inline uint32_t tf_rotl(uint32_t v, int r) {
    return (v << r) | (v >> (32 - r));
}

__host__ __device__ inline void tf_block(uint32_t k0, uint32_t k1,
                                         uint32_t c0, uint32_t c1,
                                         uint32_t& o0, uint32_t& o1) {
    uint32_t ks2 = k0 ^ k1 ^ 0x1BD11BDAu;
    uint32_t x0 = c0 + k0, x1 = c1 + k1;
#define TF_RND(r) { x0 += x1; x1 = tf_rotl(x1, (r)); x1 ^= x0; }
    TF_RND(13) TF_RND(15) TF_RND(26) TF_RND(6)
    x0 += k1;  x1 += ks2 + 1u;
    TF_RND(17) TF_RND(29) TF_RND(16) TF_RND(24)
    x0 += ks2; x1 += k0 + 2u;
    TF_RND(13) TF_RND(15) TF_RND(26) TF_RND(6)
    x0 += k0;  x1 += k1 + 3u;
    TF_RND(17) TF_RND(29) TF_RND(16) TF_RND(24)
    x0 += k1;  x1 += ks2 + 4u;
    TF_RND(13) TF_RND(15) TF_RND(26) TF_RND(6)
    x0 += ks2; x1 += k0 + 5u;
#undef TF_RND
    o0 = x0; o1 = x1;
}

__device__ inline float tf_uniform(uint32_t k0, uint32_t k1, uint32_t e) {
    uint32_t b1, b2;
    tf_block(k0, k1, 0u, e, b1, b2);
    uint32_t bits = b1 ^ b2;
    return __uint_as_float((bits >> 9) | 0x3f800000u) - 1.0f;
}

// ---------------- Kernel 1: layer-0 input trace ----------------
__global__ void trace_kernel(const float* __restrict__ inp) {
    __shared__ float filt[TAU * NB];
    int tid = threadIdx.x;
    if (tid < TAU * NB) {
        int t = tid / NB, b = tid % NB;
        const float mupi = 1.5707963267948966f;
        const float pif  = 3.14159265358979f;
        float arg = mupi * log1pf((float)t) - mupi * (float)b;
        arg = fminf(fmaxf(arg, -pif), pif);
        filt[tid] = 0.5f * (1.0f + cosf(arg));
    }
    __syncthreads();
    int i = blockIdx.x * blockDim.x + tid;
    if (i < NN) {
        float acc[NB];
#pragma unroll
        for (int b = 0; b < NB; b++) acc[b] = 0.0f;
#pragma unroll
        for (int t = 0; t < TAU; t++) {
            float v = inp[i * TAU + (TAU - 1 - t)];
#pragma unroll
            for (int b = 0; b < NB; b++) acc[b] += v * filt[t * NB + b];
        }
#pragma unroll
        for (int b = 0; b < NB; b++) g_x[0][i * NB + b] = acc[b];
    }
}

// ---------------- Kernel 2: one SNN layer, 2 rows/block, single wave -------
// grid = 1024 blocks x 256 threads, all resident (launch_bounds occ=7/SM),
// so there is no partial-wave drain tail; every block streams 128KB.
__global__ __launch_bounds__(256, 7) void layer_kernel(
    const float* __restrict__ W, const float* __restrict__ bias,
    int x_idx, int xnext_idx,
    float* __restrict__ p_out, float* __restrict__ s_out,
    uint32_t key0, uint32_t key1, float f1)
{
    __shared__ float warpsum[8];
    const float4* __restrict__ x4 =
        reinterpret_cast<const float4*>(&g_x[x_idx][0]);

#pragma unroll 1
    for (int r = 0; r < 2; r++) {
        const int row = blockIdx.x * 2 + r;
        const float4* __restrict__ w4 =
            reinterpret_cast<const float4*>(W + (size_t)row * KK);

        float acc = 0.0f;
#pragma unroll 4
        for (int it = 0; it < 16; it++) {
            int j = it * 256 + threadIdx.x;
            float4 w = __ldcs(&w4[j]);   // stream weights, evict-first
            float4 xv = x4[j];           // x stays L2-resident
            acc += w.x * xv.x + w.y * xv.y + w.z * xv.z + w.w * xv.w;
        }

        // block reduce
#pragma unroll
        for (int off = 16; off > 0; off >>= 1)
            acc += __shfl_down_sync(0xffffffffu, acc, off);
        int lane = threadIdx.x & 31, wid = threadIdx.x >> 5;
        if (lane == 0) warpsum[wid] = acc;
        __syncthreads();

        if (threadIdx.x == 0) {
            float tot = 0.0f;
#pragma unroll
            for (int w = 0; w < 8; w++) tot += warpsum[w];
            float z = tot + bias[row];
            float p = 1.0f / (1.0f + expf(-z));
            float u = tf_uniform(key0, key1, (uint32_t)row);
            float s = (u < p) ? 1.0f : 0.0f;
            p_out[row] = p;
            s_out[row] = s;
            if (xnext_idx >= 0) {
                float* xn = &g_x[xnext_idx][row * 8];
                xn[0] = s;          // FF_FILT[0,0] == 1 exactly
                xn[1] = s * f1;     // FF_FILT[0,1] == 0.5
#pragma unroll
                for (int b = 2; b < 8; b++) xn[b] = 0.0f;  // exact zeros
            }
        }
        __syncthreads();   // protect warpsum reuse across rows
    }
}

extern "C" void kernel_launch(void* const* d_in, const int* in_sizes, int n_in,
                              void* d_out, int out_size) {
    const float* inp  = (const float*)d_in[0];
    const float* ffw0 = (const float*)d_in[1];
    const float* b0   = (const float*)d_in[3];
    const float* ffw1 = (const float*)d_in[4];
    const float* b1   = (const float*)d_in[6];
    const float* ffw2 = (const float*)d_in[7];
    const float* b2   = (const float*)d_in[9];
    float* out = (float*)d_out;

    // root key = (0, 42); partitionable split: key_i = block(root, (0, i))
    uint32_t k0a, k0b, k1a, k1b, k2a, k2b;
    tf_block(0u, 42u, 0u, 0u, k0a, k0b);
    tf_block(0u, 42u, 0u, 1u, k1a, k1b);
    tf_block(0u, 42u, 0u, 2u, k2a, k2b);

    // FF_FILT[0, 1]; b>=2 entries are exactly 0 (clip to -pi), b=0 is 1.0
    const float mupi = 1.5707963267948966f;
    const float pif  = 3.14159265358979f;
    float f1 = 0.5f * (1.0f + cosf(fminf(fmaxf(-mupi, -pif), pif)));  // 0.5

    // output layout: [p2 | s2 | p0 | p1 | s0 | s1], 6 * 2048 floats
    float* p2 = out;
    float* s2 = out + 2048;
    float* p0 = out + 4096;
    float* p1 = out + 6144;
    float* s0 = out + 8192;
    float* s1 = out + 10240;

    trace_kernel<<<16, 128>>>(inp);
    layer_kernel<<<NN / 2, 256>>>(ffw0, b0, 0,  1, p0, s0, k0a, k0b, f1);
    layer_kernel<<<NN / 2, 256>>>(ffw1, b1, 1,  2, p1, s1, k1a, k1b, f1);
    layer_kernel<<<NN / 2, 256>>>(ffw2, b2, 2, -1, p2, s2, k2a, k2b, f1);
}

// round 4
// speedup vs baseline: 1.2451x; 1.0725x over previous
#include <cuda_runtime.h>
#include <math.h>
#include <stdint.h>

#define NN   2048
#define KK   16384      // NN * 8
#define TAU  10
#define NB   8

// dense trace vector for layer 0
__device__ __align__(16) float g_x0[KK];
// spike bitmasks: g_bits[0] = layer-0 spikes (input of layer 1),
//                 g_bits[1] = layer-1 spikes (input of layer 2)
__device__ unsigned int g_bits[2][NN / 32];

// ---------------- Threefry-2x32 (JAX-compatible, 20 rounds) ----------------
__host__ __device__ inline uint32_t tf_rotl(uint32_t v, int r) {
    return (v << r) | (v >> (32 - r));
}

__host__ __device__ inline void tf_block(uint32_t k0, uint32_t k1,
                                         uint32_t c0, uint32_t c1,
                                         uint32_t& o0, uint32_t& o1) {
    uint32_t ks2 = k0 ^ k1 ^ 0x1BD11BDAu;
    uint32_t x0 = c0 + k0, x1 = c1 + k1;
#define TF_RND(r) { x0 += x1; x1 = tf_rotl(x1, (r)); x1 ^= x0; }
    TF_RND(13) TF_RND(15) TF_RND(26) TF_RND(6)
    x0 += k1;  x1 += ks2 + 1u;
    TF_RND(17) TF_RND(29) TF_RND(16) TF_RND(24)
    x0 += ks2; x1 += k0 + 2u;
    TF_RND(13) TF_RND(15) TF_RND(26) TF_RND(6)
    x0 += k0;  x1 += k1 + 3u;
    TF_RND(17) TF_RND(29) TF_RND(16) TF_RND(24)
    x0 += k1;  x1 += ks2 + 4u;
    TF_RND(13) TF_RND(15) TF_RND(26) TF_RND(6)
    x0 += ks2; x1 += k0 + 5u;
#undef TF_RND
    o0 = x0; o1 = x1;
}

__device__ inline float tf_uniform(uint32_t k0, uint32_t k1, uint32_t e) {
    uint32_t b1, b2;
    tf_block(k0, k1, 0u, e, b1, b2);
    uint32_t bits = b1 ^ b2;
    return __uint_as_float((bits >> 9) | 0x3f800000u) - 1.0f;
}

// ---------------- Kernel 1: layer-0 input trace (+ zero the bitmasks) -----
__global__ void trace_kernel(const float* __restrict__ inp) {
    __shared__ float filt[TAU * NB];
    int tid = threadIdx.x;
    if (blockIdx.x == 0 && tid < 2 * (NN / 32)) {
        ((unsigned int*)g_bits)[tid] = 0u;
    }
    if (tid < TAU * NB) {
        int t = tid / NB, b = tid % NB;
        const float mupi = 1.5707963267948966f;
        const float pif  = 3.14159265358979f;
        float arg = mupi * log1pf((float)t) - mupi * (float)b;
        arg = fminf(fmaxf(arg, -pif), pif);
        filt[tid] = 0.5f * (1.0f + cosf(arg));
    }
    __syncthreads();
    int i = blockIdx.x * blockDim.x + tid;
    if (i < NN) {
        float acc[NB];
#pragma unroll
        for (int b = 0; b < NB; b++) acc[b] = 0.0f;
#pragma unroll
        for (int t = 0; t < TAU; t++) {
            float v = inp[i * TAU + (TAU - 1 - t)];
#pragma unroll
            for (int b = 0; b < NB; b++) acc[b] += v * filt[t * NB + b];
        }
#pragma unroll
        for (int b = 0; b < NB; b++) g_x0[i * NB + b] = acc[b];
    }
}

// ---------------- Kernel 2: layer 0, dense matvec (round-1 config) --------
__global__ __launch_bounds__(256) void layer0_kernel(
    const float* __restrict__ W, const float* __restrict__ bias,
    float* __restrict__ p_out, float* __restrict__ s_out,
    uint32_t key0, uint32_t key1)
{
    const int row = blockIdx.x;
    const float4* w4 = reinterpret_cast<const float4*>(W + (size_t)row * KK);
    const float4* x4 = reinterpret_cast<const float4*>(g_x0);

    float acc = 0.0f;
#pragma unroll
    for (int it = 0; it < 16; it++) {
        int j = it * 256 + threadIdx.x;
        float4 w = w4[j];
        float4 xv = x4[j];
        acc += w.x * xv.x + w.y * xv.y + w.z * xv.z + w.w * xv.w;
    }

#pragma unroll
    for (int off = 16; off > 0; off >>= 1)
        acc += __shfl_down_sync(0xffffffffu, acc, off);

    __shared__ float warpsum[8];
    int lane = threadIdx.x & 31, wid = threadIdx.x >> 5;
    if (lane == 0) warpsum[wid] = acc;
    __syncthreads();

    if (threadIdx.x == 0) {
        float tot = 0.0f;
#pragma unroll
        for (int w = 0; w < 8; w++) tot += warpsum[w];
        float z = tot + bias[row];
        float p = 1.0f / (1.0f + expf(-z));
        float u = tf_uniform(key0, key1, (uint32_t)row);
        float s = (u < p) ? 1.0f : 0.0f;
        p_out[row] = p;
        s_out[row] = s;
        if (s > 0.0f)
            atomicOr(&g_bits[0][row >> 5], 1u << (row & 31));
    }
}

// ---------------- Kernel 3: layers 1/2 — bitmask matvec -------------------
// pot[row] = sum over spiking i of (W[row,i,0] + f1 * W[row,i,1]).
// Only 8 bytes of each 32B group are read (the rest multiply exact zeros),
// and the x-vector is replaced by a 256B smem bitmask -> no L2 x stream.
__global__ __launch_bounds__(256) void layer_sparse(
    const float* __restrict__ W, const float* __restrict__ bias,
    int mask_in, int mask_out,
    float* __restrict__ p_out, float* __restrict__ s_out,
    uint32_t key0, uint32_t key1, float f1)
{
    __shared__ unsigned int sm_bits[NN / 32];
    __shared__ float warpsum[8];
    if (threadIdx.x < NN / 32) sm_bits[threadIdx.x] = g_bits[mask_in][threadIdx.x];
    __syncthreads();

    const int row = blockIdx.x;
    const float2* __restrict__ w2 =
        reinterpret_cast<const float2*>(W + (size_t)row * KK);

    float acc = 0.0f;
#pragma unroll
    for (int it = 0; it < 8; it++) {
        int i = it * 256 + threadIdx.x;           // input index
        float2 v = __ldcs(&w2[(size_t)i * 4]);    // W[row,i,0..1]
        unsigned int bit = (sm_bits[i >> 5] >> (i & 31)) & 1u;
        float m = bit ? 1.0f : 0.0f;
        acc += m * (v.x + f1 * v.y);
    }

#pragma unroll
    for (int off = 16; off > 0; off >>= 1)
        acc += __shfl_down_sync(0xffffffffu, acc, off);
    int lane = threadIdx.x & 31, wid = threadIdx.x >> 5;
    if (lane == 0) warpsum[wid] = acc;
    __syncthreads();

    if (threadIdx.x == 0) {
        float tot = 0.0f;
#pragma unroll
        for (int w = 0; w < 8; w++) tot += warpsum[w];
        float z = tot + bias[row];
        float p = 1.0f / (1.0f + expf(-z));
        float u = tf_uniform(key0, key1, (uint32_t)row);
        float s = (u < p) ? 1.0f : 0.0f;
        p_out[row] = p;
        s_out[row] = s;
        if (mask_out >= 0 && s > 0.0f)
            atomicOr(&g_bits[mask_out][row >> 5], 1u << (row & 31));
    }
}

extern "C" void kernel_launch(void* const* d_in, const int* in_sizes, int n_in,
                              void* d_out, int out_size) {
    const float* inp  = (const float*)d_in[0];
    const float* ffw0 = (const float*)d_in[1];
    const float* b0   = (const float*)d_in[3];
    const float* ffw1 = (const float*)d_in[4];
    const float* b1   = (const float*)d_in[6];
    const float* ffw2 = (const float*)d_in[7];
    const float* b2   = (const float*)d_in[9];
    float* out = (float*)d_out;

    // root key = (0, 42); partitionable split: key_i = block(root, (0, i))
    uint32_t k0a, k0b, k1a, k1b, k2a, k2b;
    tf_block(0u, 42u, 0u, 0u, k0a, k0b);
    tf_block(0u, 42u, 0u, 1u, k1a, k1b);
    tf_block(0u, 42u, 0u, 2u, k2a, k2b);

    // FF_FILT[0,1]; entries b>=2 are exactly 0 (clip to -pi), b=0 is exactly 1
    const float mupi = 1.5707963267948966f;
    const float pif  = 3.14159265358979f;
    float f1 = 0.5f * (1.0f + cosf(fminf(fmaxf(-mupi, -pif), pif)));  // ~0.5

    // output layout: [p2 | s2 | p0 | p1 | s0 | s1], 6 * 2048 floats
    float* p2 = out;
    float* s2 = out + 2048;
    float* p0 = out + 4096;
    float* p1 = out + 6144;
    float* s0 = out + 8192;
    float* s1 = out + 10240;

    trace_kernel<<<16, 128>>>(inp);
    layer0_kernel<<<NN, 256>>>(ffw0, b0, p0, s0, k0a, k0b);
    layer_sparse<<<NN, 256>>>(ffw1, b1, 0,  1, p1, s1, k1a, k1b, f1);
    layer_sparse<<<NN, 256>>>(ffw2, b2, 1, -1, p2, s2, k2a, k2b, f1);
}